// round 6
// baseline (speedup 1.0000x reference)
#include <cuda_runtime.h>
#include <cuda_pipeline.h>
#include <math.h>
#include <stdint.h>

// ---------------- problem constants ----------------
#define N_TRY 100000
#define HH    200
#define SS    30
#define AA    6
#define TT    12
#define XD    236          // H + S + A
#define XDP   240          // padded K
#define XSTR  244          // X row stride floats (61 float4s, odd -> conflict-free)
#define MT    128          // trials per block
#define NTH   800          // 25 warps
#define BK    24           // W_rssm k-tile rows (10 tiles)
#define NTILE (XDP / BK)   // 10
#define NKEEP 100
#define NBLK  ((N_TRY + MT - 1) / MT)   // 782

#define RN 8               // cols per thread (4 f32x2 pairs), 25 col-groups

// ---------------- smem layout (floats) ----------------
#define OFF_X     0
#define OFF_WT    (MT * XSTR)                    // 31232
#define OFF_WMS   (OFF_WT + 2 * BK * HH)         // +9600
#define OFF_BR    (OFF_WMS + HH * 2 * SS)        // +12000
#define OFF_BMS   (OFF_BR  + HH)
#define OFF_WRW   (OFF_BMS + 2 * SS)             // [232]
#define OFF_RSUM  (OFF_WRW + 232)
#define OFF_RPART (OFF_RSUM + MT)
#define SMEM_FLOATS (OFF_RPART + 4 * MT)         // ~54K floats = ~211 KB

// ---------------- device scratch ----------------
__device__ float g_rew[N_TRY];
__device__ int   g_topidx[NKEEP];

typedef unsigned long long ull;

__device__ __forceinline__ ull pack2(float lo, float hi) {
    ull r; asm("mov.b64 %0, {%1, %2};" : "=l"(r) : "f"(lo), "f"(hi)); return r;
}
__device__ __forceinline__ void unpack2(ull v, float& lo, float& hi) {
    asm("mov.b64 {%0, %1}, %2;" : "=f"(lo), "=f"(hi) : "l"(v));
}
__device__ __forceinline__ ull ffma2(ull a, ull b, ull c) {
    ull d; asm("fma.rn.f32x2 %0, %1, %2, %3;" : "=l"(d) : "l"(a), "l"(b), "l"(c)); return d;
}

__device__ __forceinline__ float softplusf(float x) {
    return (x > 20.0f) ? x : log1pf(expf(x));
}

// fast tanh: exp-based, abs err ~1e-7 (MUFU.TANH's 6e-4 would risk the ranking)
__device__ __forceinline__ float fast_tanh(float x) {
    float ax = fabsf(x);
    float t  = __expf(-2.0f * ax);
    float y  = __fdividef(1.0f - t, 1.0f + t);
    return copysignf(fminf(y, 1.0f), x);
}

// ============================================================================
// Kernel 1: persistent rollout, 800 threads / 128 trials per block, f32x2 math.
// Main GEMM mapping: warp w owns col-group ng=w (8 cols), lane owns 4 rows
// (lane, lane+32, lane+64, lane+96). W loads are warp-broadcast LDS.128.
// ============================================================================
__global__ void __launch_bounds__(NTH, 1)
rollout_kernel(const float* __restrict__ act_mus,  const float* __restrict__ act_sigmas,
               const float* __restrict__ eps_a,    const float* __restrict__ eps_s,
               const float* __restrict__ W_rssm,   const float* __restrict__ b_rssm,
               const float* __restrict__ W_mu,     const float* __restrict__ b_mu,
               const float* __restrict__ W_sig,    const float* __restrict__ b_sig,
               const float* __restrict__ W_rew,    const float* __restrict__ b_rew)
{
    extern __shared__ float smf[];
    float* Xs   = smf + OFF_X;     // [MT][XSTR]: 0..199 h, 200..229 s, 230..235 a, 236..243 zero
    float* Wms  = smf + OFF_WMS;   // [200][60] interleaved (mu0,sig0,...)
    float* Brs  = smf + OFF_BR;
    float* Bms  = smf + OFF_BMS;   // packed (b_mu_j, b_sig_j)
    float* Wrw  = smf + OFF_WRW;   // [232], entries 230,231 = 0
    float* Rsum = smf + OFF_RSUM;  // [MT]
    float* Rprt = smf + OFF_RPART; // [MT*4]

    const int tid = threadIdx.x;
    const int m0  = blockIdx.x * MT;

    // --- one-time init ---
    for (int i = tid; i < HH * SS; i += NTH) {
        int k = i / SS, j = i - k * SS;
        Wms[k * 60 + 2 * j]     = W_mu[i];
        Wms[k * 60 + 2 * j + 1] = W_sig[i];
    }
    for (int i = tid; i < HH;      i += NTH) Brs[i] = b_rssm[i];
    for (int i = tid; i < SS;      i += NTH) { Bms[2*i] = b_mu[i]; Bms[2*i+1] = b_sig[i]; }
    for (int i = tid; i < 232;     i += NTH) Wrw[i] = (i < HH + SS) ? W_rew[i] : 0.0f;
    for (int i = tid; i < MT * XSTR; i += NTH) Xs[i] = 0.0f;
    if (tid < MT) Rsum[tid] = 0.0f;
    const float brew = b_rew[0];
    __syncthreads();

    const int mg = tid & 31;         // rows mg, mg+32, mg+64, mg+96
    const int ng = tid >> 5;         // 0..24 (uniform within warp)
    const int nb = ng * RN;          // 32B aligned

    const float4* Wg = (const float4*)W_rssm;   // 50 float4 per row, 236 rows

    for (int t = 0; t < TT; t++) {
        // ---- actions a = mu + sigma * eps into X[:,230:236] ----
        for (int i = tid; i < MT * AA; i += NTH) {
            int m = i / AA, a = i - m * AA;
            int trial = m0 + m;
            float e = (trial < N_TRY) ? eps_a[((size_t)t * N_TRY + trial) * AA + a] : 0.0f;
            Xs[m * XSTR + (HH + SS) + a] = fmaf(act_sigmas[t * AA + a], e, act_mus[t * AA + a]);
        }
        __syncthreads();

        // ---- main GEMM: h_new = tanh(X @ W_rssm + b), f32x2 packed ----
        ull acc[4][4];               // 4 rows x 4 pairs (8 cols)
        {
            const ulonglong2* bp = (const ulonglong2*)(Brs + nb);
            ulonglong2 b0 = bp[0], b1 = bp[1];
            #pragma unroll
            for (int r = 0; r < 4; r++) {
                acc[r][0] = b0.x; acc[r][1] = b0.y;
                acc[r][2] = b1.x; acc[r][3] = b1.y;
            }
        }

        // prefetch tile 0 (rows 0..23, all valid)
        {
            float4* dst = (float4*)(smf + OFF_WT);
            for (int i = tid; i < BK * 50; i += NTH)
                __pipeline_memcpy_async(dst + i, Wg + i, 16);
            __pipeline_commit();
        }

        for (int tl = 0; tl < NTILE; tl++) {
            if (tl + 1 < NTILE) {
                int base = (tl + 1) * BK * 50;
                float4* dst = (float4*)(smf + OFF_WT + ((tl + 1) & 1) * (BK * HH));
                for (int i = tid; i < BK * 50; i += NTH) {
                    if (base + i < XD * 50) __pipeline_memcpy_async(dst + i, Wg + base + i, 16);
                    else                    dst[i] = make_float4(0.f, 0.f, 0.f, 0.f);
                }
                __pipeline_commit();
                __pipeline_wait_prior(1);
            } else {
                __pipeline_wait_prior(0);
            }
            __syncthreads();

            const float* wt = smf + OFF_WT + (tl & 1) * (BK * HH);
            const float* xb = Xs + mg * XSTR + tl * BK;
            #pragma unroll
            for (int k4 = 0; k4 < BK / 4; k4++) {
                float4 xv0 = *(const float4*)(xb + k4 * 4);
                float4 xv1 = *(const float4*)(xb + 32 * XSTR + k4 * 4);
                float4 xv2 = *(const float4*)(xb + 64 * XSTR + k4 * 4);
                float4 xv3 = *(const float4*)(xb + 96 * XSTR + k4 * 4);
                #pragma unroll
                for (int kk = 0; kk < 4; kk++) {
                    ull x0 = pack2((&xv0.x)[kk], (&xv0.x)[kk]);
                    ull x1 = pack2((&xv1.x)[kk], (&xv1.x)[kk]);
                    ull x2 = pack2((&xv2.x)[kk], (&xv2.x)[kk]);
                    ull x3 = pack2((&xv3.x)[kk], (&xv3.x)[kk]);
                    const ulonglong2* wr =
                        (const ulonglong2*)(wt + (k4 * 4 + kk) * HH + nb);
                    ulonglong2 wa = wr[0];      // cols nb..nb+3 (2 pairs)
                    ulonglong2 wb2 = wr[1];     // cols nb+4..nb+7
                    acc[0][0] = ffma2(x0, wa.x,  acc[0][0]);
                    acc[0][1] = ffma2(x0, wa.y,  acc[0][1]);
                    acc[0][2] = ffma2(x0, wb2.x, acc[0][2]);
                    acc[0][3] = ffma2(x0, wb2.y, acc[0][3]);
                    acc[1][0] = ffma2(x1, wa.x,  acc[1][0]);
                    acc[1][1] = ffma2(x1, wa.y,  acc[1][1]);
                    acc[1][2] = ffma2(x1, wb2.x, acc[1][2]);
                    acc[1][3] = ffma2(x1, wb2.y, acc[1][3]);
                    acc[2][0] = ffma2(x2, wa.x,  acc[2][0]);
                    acc[2][1] = ffma2(x2, wa.y,  acc[2][1]);
                    acc[2][2] = ffma2(x2, wb2.x, acc[2][2]);
                    acc[2][3] = ffma2(x2, wb2.y, acc[2][3]);
                    acc[3][0] = ffma2(x3, wa.x,  acc[3][0]);
                    acc[3][1] = ffma2(x3, wa.y,  acc[3][1]);
                    acc[3][2] = ffma2(x3, wb2.x, acc[3][2]);
                    acc[3][3] = ffma2(x3, wb2.y, acc[3][3]);
                }
            }
            __syncthreads();
        }

        // tanh epilogue: 4 rows x 8 cols, two STS.128 per row
        #pragma unroll
        for (int r = 0; r < 4; r++) {
            float* xr = Xs + (mg + r * 32) * XSTR + nb;
            float a0, a1, a2, a3, a4, a5, a6, a7;
            unpack2(acc[r][0], a0, a1);
            unpack2(acc[r][1], a2, a3);
            unpack2(acc[r][2], a4, a5);
            unpack2(acc[r][3], a6, a7);
            float4 v0, v1;
            v0.x = fast_tanh(a0); v0.y = fast_tanh(a1);
            v0.z = fast_tanh(a2); v0.w = fast_tanh(a3);
            v1.x = fast_tanh(a4); v1.y = fast_tanh(a5);
            v1.z = fast_tanh(a6); v1.w = fast_tanh(a7);
            *(float4*)(xr)     = v0;
            *(float4*)(xr + 4) = v1;
        }
        __syncthreads();

        // ---- s-GEMM: [128x200] @ [200x60] with (mu,sig) f32x2 pairs ----
        {
            const int m  = tid & 127;
            const int sg = tid >> 7;          // 0..6; active groups 0..4
            if (sg < 5) {
                ull a2[6];
                {
                    const ulonglong2* bp = (const ulonglong2*)(Bms + sg * 12);
                    ulonglong2 b0 = bp[0], b1 = bp[1], b2 = bp[2];
                    a2[0] = b0.x; a2[1] = b0.y; a2[2] = b1.x;
                    a2[3] = b1.y; a2[4] = b2.x; a2[5] = b2.y;
                }
                const float* hr = Xs + m * XSTR;
                const float* wb = Wms + sg * 12;
                #pragma unroll 2
                for (int k4 = 0; k4 < HH / 4; k4++) {
                    float4 hv = *(const float4*)(hr + k4 * 4);
                    #pragma unroll
                    for (int kk = 0; kk < 4; kk++) {
                        ull hp = pack2((&hv.x)[kk], (&hv.x)[kk]);
                        const ulonglong2* wr =
                            (const ulonglong2*)(wb + (k4 * 4 + kk) * 60);
                        ulonglong2 w0 = wr[0], w1 = wr[1], w2 = wr[2];
                        a2[0] = ffma2(hp, w0.x, a2[0]);
                        a2[1] = ffma2(hp, w0.y, a2[1]);
                        a2[2] = ffma2(hp, w1.x, a2[2]);
                        a2[3] = ffma2(hp, w1.y, a2[3]);
                        a2[4] = ffma2(hp, w2.x, a2[4]);
                        a2[5] = ffma2(hp, w2.y, a2[5]);
                    }
                }
                const int trial = m0 + m;
                float* so = Xs + m * XSTR + HH + sg * 6;
                #pragma unroll
                for (int u = 0; u < 6; u++) {
                    float amu, asg;
                    unpack2(a2[u], amu, asg);
                    float e = 0.0f;
                    if (trial < N_TRY)
                        e = eps_s[((size_t)t * N_TRY + trial) * SS + sg * 6 + u];
                    so[u] = fmaf(softplusf(asg), e, amu);
                }
            }
        }
        __syncthreads();

        // ---- reward: [h|s] . W_rew, 4 threads per trial, f32x2 packed ----
        if (tid < 4 * MT) {
            const int m = tid >> 2, q = tid & 3;
            const int kb = q * 58;                 // 232 = 4*58, Wrw[230..231]=0
            ull racc = 0ull;
            const float* xr = Xs + m * XSTR;
            #pragma unroll 2
            for (int k2 = 0; k2 < 58; k2 += 2) {
                ull xv = *(const ull*)(xr + kb + k2);
                ull wv = *(const ull*)(Wrw + kb + k2);
                racc = ffma2(xv, wv, racc);
            }
            float rlo, rhi;
            unpack2(racc, rlo, rhi);
            Rprt[tid] = rlo + rhi;
        }
        __syncthreads();
        if (tid < MT)
            Rsum[tid] += ((Rprt[4*tid] + Rprt[4*tid+1]) + (Rprt[4*tid+2] + Rprt[4*tid+3])) + brew;
        __syncthreads();
    }

    if (tid < MT) {
        int trial = m0 + tid;
        if (trial < N_TRY) g_rew[trial] = Rsum[tid];
    }
}

// ============================================================================
// Kernel 2: exact top-100, lax.top_k semantics (value desc, index asc).
// ============================================================================
__device__ __forceinline__ unsigned f2key(float f) {
    unsigned u = __float_as_uint(f);
    return (u & 0x80000000u) ? ~u : (u | 0x80000000u);
}

__global__ void topk_kernel(float* __restrict__ out)
{
    __shared__ unsigned hist[256];
    __shared__ unsigned sh_prefix, sh_need;
    __shared__ int cntAbove, cntEq;
    __shared__ int      aboveIdx[128];
    __shared__ unsigned aboveKey[128];
    __shared__ int      eqIdx[256];
    __shared__ unsigned long long skey[128];
    __shared__ int      sidx[128];

    const int tid = threadIdx.x;
    const int nt  = blockDim.x;

    if (tid == 0) { sh_prefix = 0u; sh_need = NKEEP; }

    for (int shift = 24; shift >= 0; shift -= 8) {
        for (int i = tid; i < 256; i += nt) hist[i] = 0u;
        __syncthreads();
        unsigned prefix = sh_prefix;
        unsigned himask = (shift == 24) ? 0u : (0xFFFFFFFFu << (shift + 8));
        for (int i = tid; i < N_TRY; i += nt) {
            unsigned u = f2key(g_rew[i]);
            if ((u & himask) == (prefix & himask))
                atomicAdd(&hist[(u >> shift) & 255u], 1u);
        }
        __syncthreads();
        if (tid == 0) {
            unsigned need = sh_need, cum = 0; int b = 255;
            for (; b >= 0; b--) { cum += hist[b]; if (cum >= need) break; }
            sh_need   = need - (cum - hist[b]);
            sh_prefix = prefix | ((unsigned)b << shift);
        }
        __syncthreads();
    }
    const unsigned Kth    = sh_prefix;
    const unsigned needEq = sh_need;

    if (tid == 0) { cntAbove = 0; cntEq = 0; }
    __syncthreads();
    for (int i = tid; i < N_TRY; i += nt) {
        unsigned u = f2key(g_rew[i]);
        if (u > Kth) {
            int p = atomicAdd(&cntAbove, 1);
            if (p < 128) { aboveIdx[p] = i; aboveKey[p] = u; }
        } else if (u == Kth) {
            int p = atomicAdd(&cntEq, 1);
            if (p < 256) eqIdx[p] = i;
        }
    }
    __syncthreads();

    int ne = min(cntEq, 256);
    for (int i = tid; i < 256; i += nt) if (i >= ne) eqIdx[i] = 0x7FFFFFFF;
    __syncthreads();
    for (int ksz = 2; ksz <= 256; ksz <<= 1)
        for (int j = ksz >> 1; j > 0; j >>= 1) {
            for (int i = tid; i < 256; i += nt) {
                int ixj = i ^ j;
                if (ixj > i) {
                    bool up = ((i & ksz) == 0);
                    int a = eqIdx[i], b = eqIdx[ixj];
                    if ((a > b) == up) { eqIdx[i] = b; eqIdx[ixj] = a; }
                }
            }
            __syncthreads();
        }

    for (int i = tid; i < 128; i += nt) {
        unsigned long long key; int idx;
        if (i < cntAbove) {
            idx = aboveIdx[i];
            key = ((unsigned long long)aboveKey[i] << 32) | (unsigned)(0xFFFFFFFFu - (unsigned)idx);
        } else if (i < cntAbove + (int)needEq) {
            idx = eqIdx[i - cntAbove];
            key = ((unsigned long long)Kth << 32) | (unsigned)(0xFFFFFFFFu - (unsigned)idx);
        } else {
            idx = 0; key = 0ull;
        }
        skey[i] = key; sidx[i] = idx;
    }
    __syncthreads();
    for (int ksz = 2; ksz <= 128; ksz <<= 1)
        for (int j = ksz >> 1; j > 0; j >>= 1) {
            for (int i = tid; i < 128; i += nt) {
                int ixj = i ^ j;
                if (ixj > i) {
                    bool up = ((i & ksz) == 0);
                    unsigned long long a = skey[i], b = skey[ixj];
                    if ((a < b) == up) {
                        skey[i] = b; skey[ixj] = a;
                        int ti = sidx[i]; sidx[i] = sidx[ixj]; sidx[ixj] = ti;
                    }
                }
            }
            __syncthreads();
        }

    if (tid < NKEEP) {
        unsigned u = (unsigned)(skey[tid] >> 32);
        unsigned bits = (u & 0x80000000u) ? (u & 0x7FFFFFFFu) : ~u;
        out[TT * NKEEP * AA + tid] = __uint_as_float(bits);
        g_topidx[tid] = sidx[tid];
    }
}

// ============================================================================
// Kernel 3: gather k_best (recompute actions on the fly).
// ============================================================================
__global__ void gather_kernel(const float* __restrict__ act_mus,
                              const float* __restrict__ act_sigmas,
                              const float* __restrict__ eps_a,
                              float* __restrict__ out)
{
    int i = blockIdx.x * blockDim.x + threadIdx.x;
    if (i >= TT * NKEEP * AA) return;
    int a = i % AA;
    int r = (i / AA) % NKEEP;
    int t = i / (AA * NKEEP);
    int idx = g_topidx[r];
    out[i] = fmaf(act_sigmas[t * AA + a],
                  eps_a[((size_t)t * N_TRY + idx) * AA + a],
                  act_mus[t * AA + a]);
}

// ============================================================================
extern "C" void kernel_launch(void* const* d_in, const int* in_sizes, int n_in,
                              void* d_out, int out_size)
{
    const float* act_mus    = (const float*)d_in[2];
    const float* act_sigmas = (const float*)d_in[3];
    const float* eps_a      = (const float*)d_in[4];
    const float* eps_s      = (const float*)d_in[5];
    const float* W_rssm     = (const float*)d_in[6];
    const float* b_rssm     = (const float*)d_in[7];
    const float* W_mu       = (const float*)d_in[8];
    const float* b_mu       = (const float*)d_in[9];
    const float* W_sig      = (const float*)d_in[10];
    const float* b_sig      = (const float*)d_in[11];
    const float* W_rew      = (const float*)d_in[12];
    const float* b_rew      = (const float*)d_in[13];
    float* out = (float*)d_out;

    const size_t smem = SMEM_FLOATS * sizeof(float);
    cudaFuncSetAttribute(rollout_kernel,
                         cudaFuncAttributeMaxDynamicSharedMemorySize, (int)smem);

    rollout_kernel<<<NBLK, NTH, smem>>>(act_mus, act_sigmas, eps_a, eps_s,
                                        W_rssm, b_rssm, W_mu, b_mu,
                                        W_sig, b_sig, W_rew, b_rew);
    topk_kernel<<<1, 1024>>>(out);
    gather_kernel<<<(TT * NKEEP * AA + 255) / 256, 256>>>(act_mus, act_sigmas, eps_a, out);
}